// round 9
// baseline (speedup 1.0000x reference)
#include <cuda_runtime.h>
#include <math.h>

// Problem constants
#define B_  32
#define C_  512
#define T_  4000
#define NV_ 1000          // T/4 float4s
#define NV8 500           // T/8 float8 chunks
#define H4C 2048          // 4*C (stats width)
#define SP1 16            // gemm1 K-splits (K=2048, chunk 128)
#define SP2 8             // gemm2 K-splits (K=512,  chunk 64)

// L2 tail persistence: last blocks (32KB of xa+xb each) mark their loads
// evict_last. 3584 * 32KB = 112MB < 126MB L2.
#define TAIL_START 12800   // bid >= TAIL_START -> evict_last (16384-3584)

// ---------------- scratch (device globals; no allocation allowed) -----------
__device__ float g_statsT[H4C * B_];          // [2048][32]  feature-major, batch=lane
__device__ float g_hT[C_ * B_];               // [512][32]
__device__ float g_p1[SP1 * C_ * B_];         // gemm1 K-split partials
__device__ float g_p2[SP2 * 2 * C_ * B_];     // gemm2 K-split partials

// 32-byte evict_last load (sm_103a requires v8.b32/v4.b64 with this modifier)
__device__ __forceinline__ void ld_evict_last8(const float* p, float v[8]) {
    unsigned long long r0, r1, r2, r3;
    asm volatile("ld.global.nc.L2::evict_last.v4.b64 {%0,%1,%2,%3}, [%4];"
                 : "=l"(r0), "=l"(r1), "=l"(r2), "=l"(r3) : "l"(p));
    v[0] = __uint_as_float((unsigned)(r0));       v[1] = __uint_as_float((unsigned)(r0 >> 32));
    v[2] = __uint_as_float((unsigned)(r1));       v[3] = __uint_as_float((unsigned)(r1 >> 32));
    v[4] = __uint_as_float((unsigned)(r2));       v[5] = __uint_as_float((unsigned)(r2 >> 32));
    v[6] = __uint_as_float((unsigned)(r3));       v[7] = __uint_as_float((unsigned)(r3 >> 32));
}

// ---------------- kernel 1: fused add + 4-moment reduction ------------------
__global__ __launch_bounds__(256) void stats_kernel(
    const float* __restrict__ xa, const float* __restrict__ xb)
{
    int c = blockIdx.x;
    int b = blockIdx.y;
    size_t base = ((size_t)(b * C_ + c)) * T_;
    bool tail = ((int)(blockIdx.y * gridDim.x + blockIdx.x)) >= TAIL_START;

    float s1 = 0.f, s2 = 0.f, s3 = 0.f, s4 = 0.f;
    if (tail) {
        // tail blocks: keep lines resident in L2 for the apply kernel
        const float* pa = xa + base;
        const float* pb = xb + base;
        for (int i = threadIdx.x; i < NV8; i += 256) {
            float av[8], bv[8];
            ld_evict_last8(pa + 8 * i, av);
            ld_evict_last8(pb + 8 * i, bv);
            #pragma unroll
            for (int q = 0; q < 8; q++) {
                float x = av[q] + bv[q];
                float x2 = x * x;
                s1 += x;
                s2 = fmaf(x, x, s2);
                s3 = fmaf(x2, x, s3);
                s4 = fmaf(x2, x2, s4);
            }
        }
    } else {
        const float4* a4 = reinterpret_cast<const float4*>(xa + base);
        const float4* b4 = reinterpret_cast<const float4*>(xb + base);
        for (int i = threadIdx.x; i < NV_; i += 256) {
            float4 av = a4[i];
            float4 bv = b4[i];
            float xv[4] = {av.x + bv.x, av.y + bv.y, av.z + bv.z, av.w + bv.w};
            #pragma unroll
            for (int q = 0; q < 4; q++) {
                float x = xv[q];
                float x2 = x * x;
                s1 += x;
                s2 = fmaf(x, x, s2);
                s3 = fmaf(x2, x, s3);
                s4 = fmaf(x2, x2, s4);
            }
        }
    }
    #pragma unroll
    for (int off = 16; off > 0; off >>= 1) {
        s1 += __shfl_down_sync(0xffffffffu, s1, off);
        s2 += __shfl_down_sync(0xffffffffu, s2, off);
        s3 += __shfl_down_sync(0xffffffffu, s3, off);
        s4 += __shfl_down_sync(0xffffffffu, s4, off);
    }
    __shared__ float red[8][4];
    int w = threadIdx.x >> 5;
    if ((threadIdx.x & 31) == 0) {
        red[w][0] = s1; red[w][1] = s2; red[w][2] = s3; red[w][3] = s4;
    }
    __syncthreads();
    if (threadIdx.x == 0) {
        float t1 = 0.f, t2 = 0.f, t3 = 0.f, t4 = 0.f;
        #pragma unroll
        for (int i = 0; i < 8; i++) {
            t1 += red[i][0]; t2 += red[i][1]; t3 += red[i][2]; t4 += red[i][3];
        }
        const float Tf = (float)T_;
        float m  = t1 / Tf;
        float m2 = m * m;
        float sc2 = t2 - t1 * m;                       // sum centered^2
        float var = fmaxf(sc2 / (Tf - 1.0f), 0.f);     // unbiased
        float sd  = sqrtf(var);
        float d   = fmaxf(sd, 0.01f);                  // EPS clamp
        float sc3 = t3 - 3.f * m * t2 + 2.f * Tf * m * m2;
        float sc4 = t4 - 4.f * m * t3 + 6.f * m2 * t2 - 3.f * Tf * m2 * m2;
        float d3inv = 1.f / (Tf * d * d * d);
        float skew = sc3 * d3inv;
        float kurt = sc4 * d3inv / d;
        g_statsT[(c)            * B_ + b] = m;
        g_statsT[(C_ + c)       * B_ + b] = sd;
        g_statsT[(2 * C_ + c)   * B_ + b] = skew;
        g_statsT[(3 * C_ + c)   * B_ + b] = kurt;
    }
}

// ---------------- mini-GEMM: out[r][b] partials = A[r][:K] . xT[:K][b]
// Weight tile (A) loaded into registers BEFORE cudaGridDependencySynchronize
// (PDL overlap of the cold DRAM fetch with the predecessor kernel).
template<int KC>
__device__ __forceinline__ void gemm_tile_pdl(
    const float* __restrict__ A, const float* __restrict__ xT,
    float* __restrict__ outP, int K, int rows)
{
    __shared__ __align__(16) float sA[32 * KC];   // [jj][k] row-major
    __shared__ __align__(16) float sX[KC * 32];   // [k][b]
    const int j0 = blockIdx.x * 32;
    const int i0 = blockIdx.y * KC;
    const int tid = threadIdx.x;

    constexpr int NF = KC / 32;   // float4s per thread for each tile
    float4 va[NF];
    #pragma unroll
    for (int t = 0; t < NF; t++) {
        int f  = tid + t * 256;            // f4 index in [0, 8*KC)
        int jj = f / (KC / 4);
        int kq = f % (KC / 4);
        va[t] = *reinterpret_cast<const float4*>(A + (size_t)(j0 + jj) * K + i0 + 4 * kq);
    }

    cudaGridDependencySynchronize();       // predecessor results now visible

    {
        float4 vx[NF];
        const float4* x4 = reinterpret_cast<const float4*>(xT + (size_t)i0 * B_);
        #pragma unroll
        for (int t = 0; t < NF; t++)
            vx[t] = x4[tid + t * 256];
        #pragma unroll
        for (int t = 0; t < NF; t++)
            reinterpret_cast<float4*>(sX)[tid + t * 256] = vx[t];
    }
    #pragma unroll
    for (int t = 0; t < NF; t++)
        reinterpret_cast<float4*>(sA)[tid + t * 256] = va[t];
    __syncthreads();

    const int b  = tid & 31;
    const int jb = (tid >> 5) * 4;     // 8 warps * 4 rows = 32 rows
    float a0 = 0.f, a1 = 0.f, a2 = 0.f, a3 = 0.f;
    #pragma unroll 8
    for (int k4 = 0; k4 < KC / 4; k4++) {
        float4 r0 = reinterpret_cast<const float4*>(sA)[(jb + 0) * (KC / 4) + k4];
        float4 r1 = reinterpret_cast<const float4*>(sA)[(jb + 1) * (KC / 4) + k4];
        float4 r2 = reinterpret_cast<const float4*>(sA)[(jb + 2) * (KC / 4) + k4];
        float4 r3 = reinterpret_cast<const float4*>(sA)[(jb + 3) * (KC / 4) + k4];
        float s0 = sX[(4 * k4 + 0) * 32 + b];
        float s1 = sX[(4 * k4 + 1) * 32 + b];
        float s2 = sX[(4 * k4 + 2) * 32 + b];
        float s3 = sX[(4 * k4 + 3) * 32 + b];
        a0 = fmaf(r0.x, s0, a0); a0 = fmaf(r0.y, s1, a0); a0 = fmaf(r0.z, s2, a0); a0 = fmaf(r0.w, s3, a0);
        a1 = fmaf(r1.x, s0, a1); a1 = fmaf(r1.y, s1, a1); a1 = fmaf(r1.z, s2, a1); a1 = fmaf(r1.w, s3, a1);
        a2 = fmaf(r2.x, s0, a2); a2 = fmaf(r2.y, s1, a2); a2 = fmaf(r2.z, s2, a2); a2 = fmaf(r2.w, s3, a2);
        a3 = fmaf(r3.x, s0, a3); a3 = fmaf(r3.y, s1, a3); a3 = fmaf(r3.z, s2, a3); a3 = fmaf(r3.w, s3, a3);
    }
    size_t obase = (size_t)blockIdx.y * rows * B_ + (size_t)(j0 + jb) * B_ + b;
    outP[obase + 0 * B_] = a0;
    outP[obase + 1 * B_] = a1;
    outP[obase + 2 * B_] = a2;
    outP[obase + 3 * B_] = a3;
}

__global__ __launch_bounds__(256) void gemm1_kernel(const float* __restrict__ W1)
{
    gemm_tile_pdl<128>(W1, g_statsT, g_p1, H4C, C_);
}

__global__ __launch_bounds__(256) void reduce1_kernel(const float* __restrict__ b1)
{
    int idx4 = blockIdx.x * 256 + threadIdx.x;    // over C_*B_/4 = 4096 float4s
    float bv = (idx4 < C_ * B_ / 4) ? b1[idx4 >> 3] : 0.f;   // input: safe pre-sync
    cudaGridDependencySynchronize();
    if (idx4 >= C_ * B_ / 4) return;
    float4 acc = make_float4(bv, bv, bv, bv);
    #pragma unroll
    for (int sp = 0; sp < SP1; sp++) {
        float4 p = reinterpret_cast<const float4*>(g_p1)[sp * (C_ * B_ / 4) + idx4];
        acc.x += p.x; acc.y += p.y; acc.z += p.z; acc.w += p.w;
    }
    reinterpret_cast<float4*>(g_hT)[idx4] = acc;
}

__global__ __launch_bounds__(256) void gemm2_kernel(const float* __restrict__ W2)
{
    gemm_tile_pdl<64>(W2, g_hT, g_p2, C_, 2 * C_);
}

// ---------------- kernel 5: gate reduce + softmax + weighted combine --------
// Reverse (c,b) order: early blocks consume the evict_last tail from L2.
// Streaming reads (__ldcs, evict-first) never displace the persisted tail;
// writes are streaming too (__stcs).
__global__ __launch_bounds__(256) void apply_kernel(
    const float* __restrict__ xa, const float* __restrict__ xb,
    const float* __restrict__ b2, float* __restrict__ out)
{
    int lin = (B_ * C_ - 1) - (int)(blockIdx.y * C_ + blockIdx.x);
    int b = lin / C_;
    int c = lin - b * C_;

    // inputs independent of predecessors: read before sync
    float s0 = b2[c];
    float s1 = b2[C_ + c];

    cudaGridDependencySynchronize();       // g_p2 now visible

    #pragma unroll
    for (int sp = 0; sp < SP2; sp++) {
        s0 += g_p2[(size_t)sp * (2 * C_ * B_) + (size_t)c * B_ + b];
        s1 += g_p2[(size_t)sp * (2 * C_ * B_) + (size_t)(C_ + c) * B_ + b];
    }
    float mx = fmaxf(s0, s1);
    float e0 = __expf(s0 - mx);
    float e1 = __expf(s1 - mx);
    float inv = 1.f / (e0 + e1);
    float g0 = e0 * inv;
    float g1 = e1 * inv;

    size_t base = ((size_t)(b * C_ + c)) * T_;
    const float4* a4 = reinterpret_cast<const float4*>(xa + base);
    const float4* b4 = reinterpret_cast<const float4*>(xb + base);
    float4* o4 = reinterpret_cast<float4*>(out + base);
    for (int i = threadIdx.x; i < NV_; i += 256) {
        float4 av = __ldcs(&a4[i]);
        float4 bv = __ldcs(&b4[i]);
        float4 r;
        r.x = fmaf(av.x, g0, bv.x * g1);
        r.y = fmaf(av.y, g0, bv.y * g1);
        r.z = fmaf(av.z, g0, bv.z * g1);
        r.w = fmaf(av.w, g0, bv.w * g1);
        __stcs(&o4[i], r);
    }
}

// ---------------- launcher --------------------------------------------------
static inline void launch_pdl(const void* fn, dim3 grid, dim3 block,
                              void** args)
{
    cudaLaunchConfig_t cfg = {};
    cfg.gridDim  = grid;
    cfg.blockDim = block;
    cfg.dynamicSmemBytes = 0;
    cfg.stream = 0;
    cudaLaunchAttribute attr[1];
    attr[0].id = cudaLaunchAttributeProgrammaticStreamSerialization;
    attr[0].val.programmaticStreamSerializationAllowed = 1;
    cfg.attrs = attr;
    cfg.numAttrs = 1;
    cudaLaunchKernelExC(&cfg, fn, args);
}

extern "C" void kernel_launch(void* const* d_in, const int* in_sizes, int n_in,
                              void* d_out, int out_size)
{
    const float* xa = (const float*)d_in[0];
    const float* xb = (const float*)d_in[1];
    const float* W1 = (const float*)d_in[2];
    const float* b1 = (const float*)d_in[3];
    const float* W2 = (const float*)d_in[4];
    const float* b2 = (const float*)d_in[5];
    float* out = (float*)d_out;

    stats_kernel<<<dim3(C_, B_), 256>>>(xa, xb);

    {   // gemm1: PDL secondary of stats (W1 preload overlaps stats tail)
        void* args[] = { (void*)&W1 };
        launch_pdl((const void*)gemm1_kernel, dim3(C_ / 32, SP1), dim3(256), args);
    }
    {   // reduce1: PDL secondary of gemm1
        void* args[] = { (void*)&b1 };
        launch_pdl((const void*)reduce1_kernel, dim3(C_ * B_ / 4 / 256), dim3(256), args);
    }
    {   // gemm2: PDL secondary of reduce1 (W2 preload overlaps)
        void* args[] = { (void*)&W2 };
        launch_pdl((const void*)gemm2_kernel, dim3(2 * C_ / 32, SP2), dim3(256), args);
    }
    {   // apply: PDL secondary of gemm2 (ramp hidden)
        void* args[] = { (void*)&xa, (void*)&xb, (void*)&b2, (void*)&out };
        launch_pdl((const void*)apply_kernel, dim3(C_, B_), dim3(256), args);
    }
}

// round 10
// speedup vs baseline: 1.1500x; 1.1500x over previous
#include <cuda_runtime.h>
#include <math.h>

// Problem constants
#define B_  32
#define C_  512
#define T_  4000
#define NV_ 1000          // T/4 float4s
#define H4C 2048          // 4*C (stats width)
#define SP1 16            // gemm1 K-splits (K=2048, chunk 128)
#define SP2 8             // gemm2 K-splits (K=512,  chunk 64)

// ---------------- scratch (device globals; no allocation allowed) -----------
__device__ float g_statsT[H4C * B_];          // [2048][32]  feature-major, batch=lane
__device__ float g_hT[C_ * B_];               // [512][32]
__device__ float g_p1[SP1 * C_ * B_];         // gemm1 K-split partials
__device__ float g_p2[SP2 * 2 * C_ * B_];     // gemm2 K-split partials

// ---------------- kernel 1: fused add + 4-moment reduction ------------------
// All 8 LDG.128 for this thread's 4 strided iterations are issued before any
// arithmetic (front-batched MLP ~ 8).
__global__ __launch_bounds__(256) void stats_kernel(
    const float* __restrict__ xa, const float* __restrict__ xb)
{
    int c = blockIdx.x;
    int b = blockIdx.y;
    size_t base = ((size_t)(b * C_ + c)) * T_;
    const float4* a4 = reinterpret_cast<const float4*>(xa + base);
    const float4* b4 = reinterpret_cast<const float4*>(xb + base);
    const int tid = threadIdx.x;

    // NV_ = 1000 = 3*256 + 232: 3 full strided iterations, 4th predicated.
    float4 av[4], bv[4];
    av[0] = a4[tid];        bv[0] = b4[tid];
    av[1] = a4[tid + 256];  bv[1] = b4[tid + 256];
    av[2] = a4[tid + 512];  bv[2] = b4[tid + 512];
    bool p3 = tid < (NV_ - 768);
    if (p3) { av[3] = a4[tid + 768]; bv[3] = b4[tid + 768]; }
    else    { av[3] = make_float4(0.f, 0.f, 0.f, 0.f);
              bv[3] = make_float4(0.f, 0.f, 0.f, 0.f); }

    float s1 = 0.f, s2 = 0.f, s3 = 0.f, s4 = 0.f;
    #pragma unroll
    for (int t = 0; t < 4; t++) {
        float xv[4] = {av[t].x + bv[t].x, av[t].y + bv[t].y,
                       av[t].z + bv[t].z, av[t].w + bv[t].w};
        #pragma unroll
        for (int q = 0; q < 4; q++) {
            float x = xv[q];
            float x2 = x * x;
            s1 += x;
            s2 = fmaf(x, x, s2);
            s3 = fmaf(x2, x, s3);
            s4 = fmaf(x2, x2, s4);
        }
    }

    #pragma unroll
    for (int off = 16; off > 0; off >>= 1) {
        s1 += __shfl_down_sync(0xffffffffu, s1, off);
        s2 += __shfl_down_sync(0xffffffffu, s2, off);
        s3 += __shfl_down_sync(0xffffffffu, s3, off);
        s4 += __shfl_down_sync(0xffffffffu, s4, off);
    }
    __shared__ float red[8][4];
    int w = tid >> 5;
    if ((tid & 31) == 0) {
        red[w][0] = s1; red[w][1] = s2; red[w][2] = s3; red[w][3] = s4;
    }
    __syncthreads();
    if (tid == 0) {
        float t1 = 0.f, t2 = 0.f, t3 = 0.f, t4 = 0.f;
        #pragma unroll
        for (int i = 0; i < 8; i++) {
            t1 += red[i][0]; t2 += red[i][1]; t3 += red[i][2]; t4 += red[i][3];
        }
        const float Tf = (float)T_;
        float m  = t1 / Tf;
        float m2 = m * m;
        float sc2 = t2 - t1 * m;                       // sum centered^2
        float var = fmaxf(sc2 / (Tf - 1.0f), 0.f);     // unbiased
        float sd  = sqrtf(var);
        float d   = fmaxf(sd, 0.01f);                  // EPS clamp
        float sc3 = t3 - 3.f * m * t2 + 2.f * Tf * m * m2;
        float sc4 = t4 - 4.f * m * t3 + 6.f * m2 * t2 - 3.f * Tf * m2 * m2;
        float d3inv = 1.f / (Tf * d * d * d);
        float skew = sc3 * d3inv;
        float kurt = sc4 * d3inv / d;
        g_statsT[(c)            * B_ + b] = m;
        g_statsT[(C_ + c)       * B_ + b] = sd;
        g_statsT[(2 * C_ + c)   * B_ + b] = skew;
        g_statsT[(3 * C_ + c)   * B_ + b] = kurt;
    }
}

// ---------------- mini-GEMM: out[r][b] partials = A[r][:K] . xT[:K][b]
// Weight tile (A) loaded into registers BEFORE cudaGridDependencySynchronize
// (PDL overlap of the cold DRAM fetch with the predecessor kernel).
template<int KC>
__device__ __forceinline__ void gemm_tile_pdl(
    const float* __restrict__ A, const float* __restrict__ xT,
    float* __restrict__ outP, int K, int rows)
{
    __shared__ __align__(16) float sA[32 * KC];   // [jj][k] row-major
    __shared__ __align__(16) float sX[KC * 32];   // [k][b]
    const int j0 = blockIdx.x * 32;
    const int i0 = blockIdx.y * KC;
    const int tid = threadIdx.x;

    constexpr int NF = KC / 32;   // float4s per thread for each tile
    float4 va[NF];
    #pragma unroll
    for (int t = 0; t < NF; t++) {
        int f  = tid + t * 256;            // f4 index in [0, 8*KC)
        int jj = f / (KC / 4);
        int kq = f % (KC / 4);
        va[t] = *reinterpret_cast<const float4*>(A + (size_t)(j0 + jj) * K + i0 + 4 * kq);
    }

    cudaGridDependencySynchronize();       // predecessor results now visible

    {
        float4 vx[NF];
        const float4* x4 = reinterpret_cast<const float4*>(xT + (size_t)i0 * B_);
        #pragma unroll
        for (int t = 0; t < NF; t++)
            vx[t] = x4[tid + t * 256];
        #pragma unroll
        for (int t = 0; t < NF; t++)
            reinterpret_cast<float4*>(sX)[tid + t * 256] = vx[t];
    }
    #pragma unroll
    for (int t = 0; t < NF; t++)
        reinterpret_cast<float4*>(sA)[tid + t * 256] = va[t];
    __syncthreads();

    const int b  = tid & 31;
    const int jb = (tid >> 5) * 4;     // 8 warps * 4 rows = 32 rows
    float a0 = 0.f, a1 = 0.f, a2 = 0.f, a3 = 0.f;
    #pragma unroll 8
    for (int k4 = 0; k4 < KC / 4; k4++) {
        float4 r0 = reinterpret_cast<const float4*>(sA)[(jb + 0) * (KC / 4) + k4];
        float4 r1 = reinterpret_cast<const float4*>(sA)[(jb + 1) * (KC / 4) + k4];
        float4 r2 = reinterpret_cast<const float4*>(sA)[(jb + 2) * (KC / 4) + k4];
        float4 r3 = reinterpret_cast<const float4*>(sA)[(jb + 3) * (KC / 4) + k4];
        float s0 = sX[(4 * k4 + 0) * 32 + b];
        float s1 = sX[(4 * k4 + 1) * 32 + b];
        float s2 = sX[(4 * k4 + 2) * 32 + b];
        float s3 = sX[(4 * k4 + 3) * 32 + b];
        a0 = fmaf(r0.x, s0, a0); a0 = fmaf(r0.y, s1, a0); a0 = fmaf(r0.z, s2, a0); a0 = fmaf(r0.w, s3, a0);
        a1 = fmaf(r1.x, s0, a1); a1 = fmaf(r1.y, s1, a1); a1 = fmaf(r1.z, s2, a1); a1 = fmaf(r1.w, s3, a1);
        a2 = fmaf(r2.x, s0, a2); a2 = fmaf(r2.y, s1, a2); a2 = fmaf(r2.z, s2, a2); a2 = fmaf(r2.w, s3, a2);
        a3 = fmaf(r3.x, s0, a3); a3 = fmaf(r3.y, s1, a3); a3 = fmaf(r3.z, s2, a3); a3 = fmaf(r3.w, s3, a3);
    }
    size_t obase = (size_t)blockIdx.y * rows * B_ + (size_t)(j0 + jb) * B_ + b;
    outP[obase + 0 * B_] = a0;
    outP[obase + 1 * B_] = a1;
    outP[obase + 2 * B_] = a2;
    outP[obase + 3 * B_] = a3;
}

__global__ __launch_bounds__(256) void gemm1_kernel(const float* __restrict__ W1)
{
    gemm_tile_pdl<128>(W1, g_statsT, g_p1, H4C, C_);
}

__global__ __launch_bounds__(256) void reduce1_kernel(const float* __restrict__ b1)
{
    int idx4 = blockIdx.x * 256 + threadIdx.x;    // over C_*B_/4 = 4096 float4s
    float bv = (idx4 < C_ * B_ / 4) ? b1[idx4 >> 3] : 0.f;   // input: safe pre-sync
    cudaGridDependencySynchronize();
    if (idx4 >= C_ * B_ / 4) return;
    float4 acc = make_float4(bv, bv, bv, bv);
    #pragma unroll
    for (int sp = 0; sp < SP1; sp++) {
        float4 p = reinterpret_cast<const float4*>(g_p1)[sp * (C_ * B_ / 4) + idx4];
        acc.x += p.x; acc.y += p.y; acc.z += p.z; acc.w += p.w;
    }
    reinterpret_cast<float4*>(g_hT)[idx4] = acc;
}

__global__ __launch_bounds__(256) void gemm2_kernel(const float* __restrict__ W2)
{
    gemm_tile_pdl<64>(W2, g_hT, g_p2, C_, 2 * C_);
}

// ---------------- kernel 5: gate reduce + softmax + weighted combine --------
// Front-batched loads (8 LDG.128), then compute, then 4 streaming stores.
__global__ __launch_bounds__(256) void apply_kernel(
    const float* __restrict__ xa, const float* __restrict__ xb,
    const float* __restrict__ b2, float* __restrict__ out)
{
    int lin = (B_ * C_ - 1) - (int)(blockIdx.y * C_ + blockIdx.x);
    int b = lin / C_;
    int c = lin - b * C_;

    // inputs independent of predecessors: read before sync
    float s0 = b2[c];
    float s1 = b2[C_ + c];

    cudaGridDependencySynchronize();       // g_p2 now visible

    #pragma unroll
    for (int sp = 0; sp < SP2; sp++) {
        s0 += g_p2[(size_t)sp * (2 * C_ * B_) + (size_t)c * B_ + b];
        s1 += g_p2[(size_t)sp * (2 * C_ * B_) + (size_t)(C_ + c) * B_ + b];
    }
    float mx = fmaxf(s0, s1);
    float e0 = __expf(s0 - mx);
    float e1 = __expf(s1 - mx);
    float inv = 1.f / (e0 + e1);
    float g0 = e0 * inv;
    float g1 = e1 * inv;

    size_t base = ((size_t)(b * C_ + c)) * T_;
    const float4* a4 = reinterpret_cast<const float4*>(xa + base);
    const float4* b4 = reinterpret_cast<const float4*>(xb + base);
    float4* o4 = reinterpret_cast<float4*>(out + base);
    const int tid = threadIdx.x;

    float4 av[4], bv[4];
    av[0] = a4[tid];        bv[0] = b4[tid];
    av[1] = a4[tid + 256];  bv[1] = b4[tid + 256];
    av[2] = a4[tid + 512];  bv[2] = b4[tid + 512];
    bool p3 = tid < (NV_ - 768);
    if (p3) { av[3] = a4[tid + 768]; bv[3] = b4[tid + 768]; }

    float4 r[4];
    #pragma unroll
    for (int t = 0; t < 4; t++) {
        r[t].x = fmaf(av[t].x, g0, bv[t].x * g1);
        r[t].y = fmaf(av[t].y, g0, bv[t].y * g1);
        r[t].z = fmaf(av[t].z, g0, bv[t].z * g1);
        r[t].w = fmaf(av[t].w, g0, bv[t].w * g1);
    }
    __stcs(&o4[tid],       r[0]);
    __stcs(&o4[tid + 256], r[1]);
    __stcs(&o4[tid + 512], r[2]);
    if (p3) __stcs(&o4[tid + 768], r[3]);
}

// ---------------- launcher --------------------------------------------------
static inline void launch_pdl(const void* fn, dim3 grid, dim3 block,
                              void** args)
{
    cudaLaunchConfig_t cfg = {};
    cfg.gridDim  = grid;
    cfg.blockDim = block;
    cfg.dynamicSmemBytes = 0;
    cfg.stream = 0;
    cudaLaunchAttribute attr[1];
    attr[0].id = cudaLaunchAttributeProgrammaticStreamSerialization;
    attr[0].val.programmaticStreamSerializationAllowed = 1;
    cfg.attrs = attr;
    cfg.numAttrs = 1;
    cudaLaunchKernelExC(&cfg, fn, args);
}

extern "C" void kernel_launch(void* const* d_in, const int* in_sizes, int n_in,
                              void* d_out, int out_size)
{
    const float* xa = (const float*)d_in[0];
    const float* xb = (const float*)d_in[1];
    const float* W1 = (const float*)d_in[2];
    const float* b1 = (const float*)d_in[3];
    const float* W2 = (const float*)d_in[4];
    const float* b2 = (const float*)d_in[5];
    float* out = (float*)d_out;

    stats_kernel<<<dim3(C_, B_), 256>>>(xa, xb);

    {   // gemm1: PDL secondary of stats (W1 preload overlaps stats tail)
        void* args[] = { (void*)&W1 };
        launch_pdl((const void*)gemm1_kernel, dim3(C_ / 32, SP1), dim3(256), args);
    }
    {   // reduce1: PDL secondary of gemm1
        void* args[] = { (void*)&b1 };
        launch_pdl((const void*)reduce1_kernel, dim3(C_ * B_ / 4 / 256), dim3(256), args);
    }
    {   // gemm2: PDL secondary of reduce1 (W2 preload overlaps)
        void* args[] = { (void*)&W2 };
        launch_pdl((const void*)gemm2_kernel, dim3(2 * C_ / 32, SP2), dim3(256), args);
    }
    {   // apply: PDL secondary of gemm2 (ramp hidden)
        void* args[] = { (void*)&xa, (void*)&xb, (void*)&b2, (void*)&out };
        launch_pdl((const void*)apply_kernel, dim3(C_, B_), dim3(256), args);
    }
}